// round 9
// baseline (speedup 1.0000x reference)
#include <cuda_runtime.h>
#include <cstdint>

#define GRIDW 480
#define NPTS 100000
#define PTOT 400000
#define NCELL (4*GRIDW*GRIDW)      // 921600
#define NSM 148
#define NTHR 384
#define NWARPS (NSM*12)            // 1776
#define NGROUP32 (PTOT/32)         // 12500 warp-groups of 32 points

// ---------------- smem layout (u32 offsets) ----------------
#define SW2 0        // W2 B-frags fp16: 4nc x 8ks x 8nt x 64 = 16384 u32
#define SW3 16384    // W3 B-frags fp16: 4nc x 4kt x 8nt x 64 = 8192 u32
#define SW1 24576    // 3*128 f32
#define SB1 24960    // 128
#define SB2 25088    // 256
#define SB3 25344    // 64
#define SMEM_U32 25408
#define SMEM_BYTES (SMEM_U32*4)    // 101632 B

// ---------------- device scratch ----------------
__device__ int g_cnt[NCELL];      // zero at load; self-resetting (scan1 clears)
__device__ int g_rank[NCELL];     // scan1: partial|flags ; scan3: (rank<<1)|solo
__device__ int g_bsum[1024];

// ---------------- helpers ----------------
__device__ __forceinline__ uint32_t f2h2(float lo, float hi) {
    uint32_t r;
    asm("cvt.rn.f16x2.f32 %0, %1, %2;" : "=r"(r) : "f"(hi), "f"(lo));
    return r;
}
__device__ __forceinline__ unsigned short f2h(float f) {
    unsigned short h;
    asm("cvt.rn.f16.f32 %0, %1;" : "=h"(h) : "f"(f));
    return h;
}
__device__ __forceinline__ void mma16(float* d, const uint32_t* a, uint32_t b0, uint32_t b1) {
    asm volatile("mma.sync.aligned.m16n8k16.row.col.f32.f16.f16.f32 "
        "{%0,%1,%2,%3},{%4,%5,%6,%7},{%8,%9},{%0,%1,%2,%3};"
        : "+f"(d[0]), "+f"(d[1]), "+f"(d[2]), "+f"(d[3])
        : "r"(a[0]), "r"(a[1]), "r"(a[2]), "r"(a[3]), "r"(b0), "r"(b1));
}
__device__ __forceinline__ void atomic_fmax(float* addr, float v) {
    if (v >= 0.0f) atomicMax((int*)addr, __float_as_int(v));
    else atomicMin((unsigned int*)addr, __float_as_uint(v));
}

// ---------------- small kernels ----------------
__global__ void k_mark(const int* __restrict__ xy) {
    int p = blockIdx.x * blockDim.x + threadIdx.x;
    if (p < PTOT) {
        int2 v = ((const int2*)xy)[p];
        int b = p / NPTS;
        atomicAdd(&g_cnt[(b * GRIDW + v.x) * GRIDW + v.y], 1);
    }
}

// per-block exclusive scan of occupancy; packs occ/solo flags; zeroes g_cnt for next replay
__global__ void k_scan1() {
    __shared__ int ws[32];
    int i = blockIdx.x * 1024 + threadIdx.x;
    int lane = threadIdx.x & 31, wid = threadIdx.x >> 5;
    int c = g_cnt[i];
    if (c) g_cnt[i] = 0;                    // self-reset (write only if dirty)
    int v = (c != 0);
    unsigned int m = __ballot_sync(0xffffffffu, v);
    int excl = __popc(m & ((1u << lane) - 1u));
    if (lane == 31) ws[wid] = excl + v;
    __syncthreads();
    if (wid == 0) {
        int x = ws[lane];
        #pragma unroll
        for (int d = 1; d < 32; d <<= 1) {
            int o = __shfl_up_sync(0xffffffffu, x, d);
            if (lane >= d) x += o;
        }
        ws[lane] = x;
    }
    __syncthreads();
    int partial = excl + (wid ? ws[wid - 1] : 0);
    g_rank[i] = partial | (v << 16) | ((c == 1) << 17);
    if (threadIdx.x == 1023) g_bsum[blockIdx.x] = ws[31];
}

// finalize ranks (block offset computed inline from g_bsum), write unq rows,
// and -inf-init pooled rows of non-solo voxels (warp-cooperative, coalesced).
__global__ void k_scan3(float* unq_out, uint2* pooled) {
    __shared__ int ws[32];
    __shared__ int s_off;
    int t = threadIdx.x;
    int lane = t & 31, wid = t >> 5;

    int v = (t < blockIdx.x && t < 900) ? g_bsum[t] : 0;
    #pragma unroll
    for (int d = 16; d > 0; d >>= 1)
        v += __shfl_xor_sync(0xffffffffu, v, d);
    if (lane == 0) ws[wid] = v;
    __syncthreads();
    if (wid == 0) {
        int x = ws[lane];
        #pragma unroll
        for (int d = 16; d > 0; d >>= 1)
            x += __shfl_xor_sync(0xffffffffu, x, d);
        if (lane == 0) s_off = x;
    }
    __syncthreads();
    int off = s_off;

    int i = blockIdx.x * 1024 + t;
    int packed = g_rank[i];
    int occ = (packed >> 16) & 1;
    int solo = (packed >> 17) & 1;
    int r = (packed & 0xFFFF) + off;
    if (occ) {
        g_rank[i] = (r << 1) | solo;
        if (unq_out) {
            int b = i / (GRIDW * GRIDW);
            int rem = i - b * GRIDW * GRIDW;
            unq_out[3 * r + 0] = (float)b;
            unq_out[3 * r + 1] = (float)(rem / GRIDW);
            unq_out[3 * r + 2] = (float)(rem % GRIDW);
        }
    }
    unsigned int nm = __ballot_sync(0xffffffffu, occ && !solo);
    uint2 ninf = make_uint2(0xff800000u, 0xff800000u);
    while (nm) {
        int src = __ffs(nm) - 1;
        nm &= nm - 1;
        int rr = __shfl_sync(0xffffffffu, r, src);
        pooled[(size_t)rr * 32 + lane] = ninf;
    }
}

// ---------------- fused fp16 mma.sync MLP, M=32/warp, L2/L3 software-pipelined ----
__global__ void __launch_bounds__(NTHR, 1)
k_mlp(const float* __restrict__ pt_fea, const int* __restrict__ xy,
      const float* __restrict__ W1g, const float* __restrict__ b1g,
      const float* __restrict__ W2g, const float* __restrict__ b2g,
      const float* __restrict__ W3g, const float* __restrict__ b3g,
      float* __restrict__ pooled) {
    extern __shared__ uint32_t sm[];
    float* smf = (float*)sm;
    int t = threadIdx.x;

    // ---- stage W2 as fp16 B-frags: sm[SW2 + ((nc*8+ks)*8+nt)*64 + lane*2 + j] ----
    for (int idx = t; idx < 16384; idx += NTHR) {
        int j = idx & 1, lane = (idx >> 1) & 31, nt = (idx >> 6) & 7,
            ks = (idx >> 9) & 7, nc = idx >> 12;
        int k = ks * 16 + (lane & 3) * 2 + j * 8;
        int n = nc * 64 + nt * 8 + (lane >> 2);
        sm[SW2 + idx] = (uint32_t)f2h(W2g[k * 256 + n]) |
                        ((uint32_t)f2h(W2g[(k + 1) * 256 + n]) << 16);
    }
    // ---- stage W3 as fp16 B-frags: sm[SW3 + ((nc*4+kt)*8+nt)*64 + lane*2 + j] ----
    for (int idx = t; idx < 8192; idx += NTHR) {
        int j = idx & 1, lane = (idx >> 1) & 31, nt = (idx >> 6) & 7,
            kt = (idx >> 9) & 3, nc = idx >> 11;
        int k = nc * 64 + kt * 16 + (lane & 3) * 2 + j * 8;
        int n = nt * 8 + (lane >> 2);
        sm[SW3 + idx] = (uint32_t)f2h(W3g[k * 64 + n]) |
                        ((uint32_t)f2h(W3g[(k + 1) * 64 + n]) << 16);
    }
    for (int i = t; i < 384; i += NTHR) smf[SW1 + i] = W1g[i];
    if (t < 128) smf[SB1 + t] = b1g[t];
    if (t < 64) { smf[SB2 + t] = b2g[t]; smf[SB2 + 64 + t] = b2g[64 + t];
                  smf[SB2 + 128 + t] = b2g[128 + t]; smf[SB2 + 192 + t] = b2g[192 + t];
                  smf[SB3 + t] = b3g[t]; }
    __syncthreads();

    const int lane = t & 31;
    const int gq = lane >> 5 ? 0 : (lane >> 2), tig = lane & 3;
    const int warp = blockIdx.x * (NTHR / 32) + (t >> 5);

    for (int grp = warp; grp < NGROUP32; grp += NWARPS) {
        int base = grp * 32;
        int p0 = base + gq, p1 = p0 + 8, p2 = p0 + 16, p3 = p0 + 24;
        int2 v0 = ((const int2*)xy)[p0];
        int2 v1 = ((const int2*)xy)[p1];
        int2 v2 = ((const int2*)xy)[p2];
        int2 v3 = ((const int2*)xy)[p3];
        int r0 = g_rank[((p0 / NPTS) * GRIDW + v0.x) * GRIDW + v0.y];
        int r1 = g_rank[((p1 / NPTS) * GRIDW + v1.x) * GRIDW + v1.y];
        int r2 = g_rank[((p2 / NPTS) * GRIDW + v2.x) * GRIDW + v2.y];
        int r3 = g_rank[((p3 / NPTS) * GRIDW + v3.x) * GRIDW + v3.y];
        float x00 = pt_fea[p0 * 3], x01 = pt_fea[p0 * 3 + 1], x02 = pt_fea[p0 * 3 + 2];
        float x10 = pt_fea[p1 * 3], x11 = pt_fea[p1 * 3 + 1], x12 = pt_fea[p1 * 3 + 2];
        float x20 = pt_fea[p2 * 3], x21 = pt_fea[p2 * 3 + 1], x22 = pt_fea[p2 * 3 + 2];
        float x30 = pt_fea[p3 * 3], x31 = pt_fea[p3 * 3 + 1], x32 = pt_fea[p3 * 3 + 2];

        // ---- layer 1 -> two m16 A-tile fragment sets ----
        uint32_t A0[8][4], A1[8][4];
        #pragma unroll
        for (int ks = 0; ks < 8; ks++) {
            #pragma unroll
            for (int h = 0; h < 2; h++) {
                int c = ks * 16 + tig * 2 + h * 8;
                float wa0 = smf[SW1 + c],       wa1 = smf[SW1 + c + 1];
                float wb0 = smf[SW1 + 128 + c], wb1 = smf[SW1 + 128 + c + 1];
                float wc0 = smf[SW1 + 256 + c], wc1 = smf[SW1 + 256 + c + 1];
                float ba = smf[SB1 + c], bb = smf[SB1 + c + 1];
                float q0a = fmaxf(fmaf(x02, wc0, fmaf(x01, wb0, fmaf(x00, wa0, ba))), 0.f);
                float q0b = fmaxf(fmaf(x02, wc1, fmaf(x01, wb1, fmaf(x00, wa1, bb))), 0.f);
                float q1a = fmaxf(fmaf(x12, wc0, fmaf(x11, wb0, fmaf(x10, wa0, ba))), 0.f);
                float q1b = fmaxf(fmaf(x12, wc1, fmaf(x11, wb1, fmaf(x10, wa1, bb))), 0.f);
                float q2a = fmaxf(fmaf(x22, wc0, fmaf(x21, wb0, fmaf(x20, wa0, ba))), 0.f);
                float q2b = fmaxf(fmaf(x22, wc1, fmaf(x21, wb1, fmaf(x20, wa1, bb))), 0.f);
                float q3a = fmaxf(fmaf(x32, wc0, fmaf(x31, wb0, fmaf(x30, wa0, ba))), 0.f);
                float q3b = fmaxf(fmaf(x32, wc1, fmaf(x31, wb1, fmaf(x30, wa1, bb))), 0.f);
                A0[ks][0 + h * 2] = f2h2(q0a, q0b);
                A0[ks][1 + h * 2] = f2h2(q1a, q1b);
                A1[ks][0 + h * 2] = f2h2(q2a, q2b);
                A1[ks][1 + h * 2] = f2h2(q3a, q3b);
            }
        }

        float acc3a[8][4], acc3b[8][4];
        #pragma unroll
        for (int n = 0; n < 8; n++)
            #pragma unroll
            for (int q = 0; q < 4; q++) { acc3a[n][q] = 0.f; acc3b[n][q] = 0.f; }

        // ---- pipelined steps s = nc*4 + kt: L2(s) interleaved with L3(s-1) ----
        uint32_t af0[4], af1[4];   // converted h2 fragments of previous step

        // compute one L2 step into acc2 regs; optionally interleave prev L3
        float aA0[4], aA1[4], aB0[4], aB1[4];

        #pragma unroll 1
        for (int s = 0; s < 16; s++) {
            int nc = s >> 2, kt = s & 3;
            const uint32_t* w2p = sm + SW2 + nc * 4096 + kt * 128 + lane * 2;
            const uint32_t* w3pp = sm + SW3 + (s - 1) * 512 + lane * 2;  // prev step
            #pragma unroll
            for (int q = 0; q < 4; q++) { aA0[q] = 0.f; aA1[q] = 0.f; aB0[q] = 0.f; aB1[q] = 0.f; }

            if (s == 0) {
                #pragma unroll
                for (int ks = 0; ks < 8; ks++) {
                    uint2 bA = *(const uint2*)(w2p + ks * 512);
                    mma16(aA0, A0[ks], bA.x, bA.y);
                    mma16(aA1, A1[ks], bA.x, bA.y);
                    uint2 bB = *(const uint2*)(w2p + ks * 512 + 64);
                    mma16(aB0, A0[ks], bB.x, bB.y);
                    mma16(aB1, A1[ks], bB.x, bB.y);
                }
            } else {
                #pragma unroll
                for (int ks = 0; ks < 8; ks++) {
                    uint2 bA = *(const uint2*)(w2p + ks * 512);
                    mma16(aA0, A0[ks], bA.x, bA.y);
                    uint2 b3 = *(const uint2*)(w3pp + ks * 64);   // L3 of prev step, nt=ks
                    mma16(acc3a[ks], af0, b3.x, b3.y);
                    mma16(aA1, A1[ks], bA.x, bA.y);
                    uint2 bB = *(const uint2*)(w2p + ks * 512 + 64);
                    mma16(aB0, A0[ks], bB.x, bB.y);
                    mma16(acc3b[ks], af1, b3.x, b3.y);
                    mma16(aB1, A1[ks], bB.x, bB.y);
                }
            }

            // convert acc2 -> af (bias + relu + fp16 pack)
            float bA0v = smf[SB2 + nc * 64 + (2 * kt) * 8 + 2 * tig];
            float bA1v = smf[SB2 + nc * 64 + (2 * kt) * 8 + 2 * tig + 1];
            float bB0v = smf[SB2 + nc * 64 + (2 * kt + 1) * 8 + 2 * tig];
            float bB1v = smf[SB2 + nc * 64 + (2 * kt + 1) * 8 + 2 * tig + 1];
            af0[0] = f2h2(fmaxf(aA0[0] + bA0v, 0.f), fmaxf(aA0[1] + bA1v, 0.f));
            af0[1] = f2h2(fmaxf(aA0[2] + bA0v, 0.f), fmaxf(aA0[3] + bA1v, 0.f));
            af0[2] = f2h2(fmaxf(aB0[0] + bB0v, 0.f), fmaxf(aB0[1] + bB1v, 0.f));
            af0[3] = f2h2(fmaxf(aB0[2] + bB0v, 0.f), fmaxf(aB0[3] + bB1v, 0.f));
            af1[0] = f2h2(fmaxf(aA1[0] + bA0v, 0.f), fmaxf(aA1[1] + bA1v, 0.f));
            af1[1] = f2h2(fmaxf(aA1[2] + bA0v, 0.f), fmaxf(aA1[3] + bA1v, 0.f));
            af1[2] = f2h2(fmaxf(aB1[0] + bB0v, 0.f), fmaxf(aB1[1] + bB1v, 0.f));
            af1[3] = f2h2(fmaxf(aB1[2] + bB0v, 0.f), fmaxf(aB1[3] + bB1v, 0.f));
        }

        // ---- drain: L3 of final step (s=15) ----
        {
            const uint32_t* w3pp = sm + SW3 + 15 * 512 + lane * 2;
            #pragma unroll
            for (int nt = 0; nt < 8; nt++) {
                uint2 b3 = *(const uint2*)(w3pp + nt * 64);
                mma16(acc3a[nt], af0, b3.x, b3.y);
                mma16(acc3b[nt], af1, b3.x, b3.y);
            }
        }

        // ---- epilogue: +b3; solo fast STG, else sign-split atomics ----
        #pragma unroll
        for (int sel = 0; sel < 4; sel++) {
            int r = (sel == 0) ? r0 : (sel == 1) ? r1 : (sel == 2) ? r2 : r3;
            const float (*acc)[4] = (sel < 2) ? acc3a : acc3b;
            int half = sel & 1;
            size_t rb = (size_t)(r >> 1) * 64;
            if (r & 1) {
                float* dst = pooled + rb;
                #pragma unroll
                for (int nt3 = 0; nt3 < 8; nt3++) {
                    int col = nt3 * 8 + 2 * tig;
                    float2 val;
                    val.x = acc[nt3][2 * half]     + smf[SB3 + col];
                    val.y = acc[nt3][2 * half + 1] + smf[SB3 + col + 1];
                    *(float2*)(dst + col) = val;
                }
            } else {
                float* dst = pooled + rb;
                #pragma unroll
                for (int nt3 = 0; nt3 < 8; nt3++) {
                    int col = nt3 * 8 + 2 * tig;
                    atomic_fmax(dst + col,     acc[nt3][2 * half]     + smf[SB3 + col]);
                    atomic_fmax(dst + col + 1, acc[nt3][2 * half + 1] + smf[SB3 + col + 1]);
                }
            }
        }
    }
}

// ---------------- host launcher ----------------
extern "C" void kernel_launch(void* const* d_in, const int* in_sizes, int n_in,
                              void* d_out, int out_size) {
    const float* pt_fea = (const float*)d_in[0];
    const int*   xy     = (const int*)d_in[1];
    const float* W1     = (const float*)d_in[2];
    const float* b1     = (const float*)d_in[3];
    const float* W2     = (const float*)d_in[4];
    const float* b2     = (const float*)d_in[5];
    const float* W3     = (const float*)d_in[6];
    const float* b3     = (const float*)d_in[7];

    int M;
    float* unq_out;
    float* pooled;
    if (out_size % 67 == 0) {
        M = out_size / 67;
        unq_out = (float*)d_out;
        pooled = (float*)d_out + (size_t)3 * M;
    } else {
        M = out_size / 64;
        unq_out = nullptr;
        pooled = (float*)d_out;
    }

    cudaFuncSetAttribute(k_mlp, cudaFuncAttributeMaxDynamicSharedMemorySize, SMEM_BYTES);

    k_mark<<<(PTOT + 255) / 256, 256>>>(xy);
    k_scan1<<<NCELL / 1024, 1024>>>();
    k_scan3<<<NCELL / 1024, 1024>>>(unq_out, (uint2*)pooled);
    k_mlp<<<NSM, NTHR, SMEM_BYTES>>>(pt_fea, xy, W1, b1, W2, b2, W3, b3, pooled);
}

// round 10
// speedup vs baseline: 1.0536x; 1.0536x over previous
#include <cuda_runtime.h>
#include <cstdint>

#define GRIDW 480
#define NPTS 100000
#define PTOT 400000
#define NCELL (4*GRIDW*GRIDW)      // 921600
#define NSM 148
#define NTHR 384
#define NWARPS (NSM*12)            // 1776
#define NGROUP (PTOT/16)           // 25000 warp-tiles of 16 points

// ---------------- smem layout (u32 offsets) ----------------
#define SW2 0        // W2 B-frags fp16: 4nc x 8ks x 8nt x 64 = 16384 u32
#define SW3 16384    // W3 B-frags fp16: 4nc x 4kt x 8nt x 64 = 8192 u32
#define SW1 24576    // 3*128 f32
#define SB1 24960    // 128
#define SB2 25088    // 256
#define SB3 25344    // 64
#define SMEM_U32 25408
#define SMEM_BYTES (SMEM_U32*4)    // 101632 B

// ---------------- device scratch ----------------
__device__ int g_cnt[NCELL];      // zero at load; self-resetting (scan1 clears)
__device__ int g_rank[NCELL];     // scan1: partial|flags ; scan3: (rank<<1)|solo
__device__ int g_bsum[1024];

// ---------------- helpers ----------------
__device__ __forceinline__ uint32_t f2h2(float lo, float hi) {
    uint32_t r;
    asm("cvt.rn.f16x2.f32 %0, %1, %2;" : "=r"(r) : "f"(hi), "f"(lo));
    return r;
}
__device__ __forceinline__ unsigned short f2h(float f) {
    unsigned short h;
    asm("cvt.rn.f16.f32 %0, %1;" : "=h"(h) : "f"(f));
    return h;
}
__device__ __forceinline__ void mma16(float* d, const uint32_t* a, uint32_t b0, uint32_t b1) {
    asm volatile("mma.sync.aligned.m16n8k16.row.col.f32.f16.f16.f32 "
        "{%0,%1,%2,%3},{%4,%5,%6,%7},{%8,%9},{%0,%1,%2,%3};"
        : "+f"(d[0]), "+f"(d[1]), "+f"(d[2]), "+f"(d[3])
        : "r"(a[0]), "r"(a[1]), "r"(a[2]), "r"(a[3]), "r"(b0), "r"(b1));
}
__device__ __forceinline__ void atomic_fmax(float* addr, float v) {
    if (v >= 0.0f) atomicMax((int*)addr, __float_as_int(v));
    else atomicMin((unsigned int*)addr, __float_as_uint(v));
}

// ---------------- small kernels ----------------
__global__ void k_mark(const int* __restrict__ xy) {
    int p = blockIdx.x * blockDim.x + threadIdx.x;
    if (p < PTOT) {
        int2 v = ((const int2*)xy)[p];
        int b = p / NPTS;
        atomicAdd(&g_cnt[(b * GRIDW + v.x) * GRIDW + v.y], 1);
    }
}

// per-block exclusive scan of occupancy; packs occ/solo flags; zeroes g_cnt for next replay
__global__ void k_scan1() {
    __shared__ int ws[32];
    int i = blockIdx.x * 1024 + threadIdx.x;
    int lane = threadIdx.x & 31, wid = threadIdx.x >> 5;
    int c = g_cnt[i];
    if (c) g_cnt[i] = 0;                    // self-reset (write only if dirty)
    int v = (c != 0);
    unsigned int m = __ballot_sync(0xffffffffu, v);
    int excl = __popc(m & ((1u << lane) - 1u));
    if (lane == 31) ws[wid] = excl + v;
    __syncthreads();
    if (wid == 0) {
        int x = ws[lane];
        #pragma unroll
        for (int d = 1; d < 32; d <<= 1) {
            int o = __shfl_up_sync(0xffffffffu, x, d);
            if (lane >= d) x += o;
        }
        ws[lane] = x;
    }
    __syncthreads();
    int partial = excl + (wid ? ws[wid - 1] : 0);
    g_rank[i] = partial | (v << 16) | ((c == 1) << 17);
    if (threadIdx.x == 1023) g_bsum[blockIdx.x] = ws[31];
}

// finalize ranks (block offset computed inline from g_bsum), write unq rows,
// and -inf-init pooled rows of non-solo voxels (warp-cooperative, coalesced).
__global__ void k_scan3(float* unq_out, uint2* pooled) {
    __shared__ int ws[32];
    __shared__ int s_off;
    int t = threadIdx.x;
    int lane = t & 31, wid = t >> 5;

    int v = (t < blockIdx.x && t < 900) ? g_bsum[t] : 0;
    #pragma unroll
    for (int d = 16; d > 0; d >>= 1)
        v += __shfl_xor_sync(0xffffffffu, v, d);
    if (lane == 0) ws[wid] = v;
    __syncthreads();
    if (wid == 0) {
        int x = ws[lane];
        #pragma unroll
        for (int d = 16; d > 0; d >>= 1)
            x += __shfl_xor_sync(0xffffffffu, x, d);
        if (lane == 0) s_off = x;
    }
    __syncthreads();
    int off = s_off;

    int i = blockIdx.x * 1024 + t;
    int packed = g_rank[i];
    int occ = (packed >> 16) & 1;
    int solo = (packed >> 17) & 1;
    int r = (packed & 0xFFFF) + off;
    if (occ) {
        g_rank[i] = (r << 1) | solo;
        if (unq_out) {
            int b = i / (GRIDW * GRIDW);
            int rem = i - b * GRIDW * GRIDW;
            unq_out[3 * r + 0] = (float)b;
            unq_out[3 * r + 1] = (float)(rem / GRIDW);
            unq_out[3 * r + 2] = (float)(rem % GRIDW);
        }
    }
    unsigned int nm = __ballot_sync(0xffffffffu, occ && !solo);
    uint2 ninf = make_uint2(0xff800000u, 0xff800000u);
    while (nm) {
        int src = __ffs(nm) - 1;
        nm &= nm - 1;
        int rr = __shfl_sync(0xffffffffu, r, src);
        pooled[(size_t)rr * 32 + lane] = ninf;
    }
}

// ---------------- fused fp16 mma.sync MLP, M=16/warp, 12 warps, reg headroom ----
__global__ void __launch_bounds__(NTHR, 1)
k_mlp(const float* __restrict__ pt_fea, const int* __restrict__ xy,
      const float* __restrict__ W1g, const float* __restrict__ b1g,
      const float* __restrict__ W2g, const float* __restrict__ b2g,
      const float* __restrict__ W3g, const float* __restrict__ b3g,
      float* __restrict__ pooled) {
    extern __shared__ uint32_t sm[];
    float* smf = (float*)sm;
    int t = threadIdx.x;

    // ---- stage W2 as fp16 B-frags: sm[SW2 + ((nc*8+ks)*8+nt)*64 + lane*2 + j] ----
    for (int idx = t; idx < 16384; idx += NTHR) {
        int j = idx & 1, lane = (idx >> 1) & 31, nt = (idx >> 6) & 7,
            ks = (idx >> 9) & 7, nc = idx >> 12;
        int k = ks * 16 + (lane & 3) * 2 + j * 8;
        int n = nc * 64 + nt * 8 + (lane >> 2);
        sm[SW2 + idx] = (uint32_t)f2h(W2g[k * 256 + n]) |
                        ((uint32_t)f2h(W2g[(k + 1) * 256 + n]) << 16);
    }
    // ---- stage W3 as fp16 B-frags: sm[SW3 + ((nc*4+kt)*8+nt)*64 + lane*2 + j] ----
    for (int idx = t; idx < 8192; idx += NTHR) {
        int j = idx & 1, lane = (idx >> 1) & 31, nt = (idx >> 6) & 7,
            kt = (idx >> 9) & 3, nc = idx >> 11;
        int k = nc * 64 + kt * 16 + (lane & 3) * 2 + j * 8;
        int n = nt * 8 + (lane >> 2);
        sm[SW3 + idx] = (uint32_t)f2h(W3g[k * 64 + n]) |
                        ((uint32_t)f2h(W3g[(k + 1) * 64 + n]) << 16);
    }
    for (int i = t; i < 384; i += NTHR) smf[SW1 + i] = W1g[i];
    if (t < 128) smf[SB1 + t] = b1g[t];
    if (t < 64) { smf[SB2 + t] = b2g[t]; smf[SB2 + 64 + t] = b2g[64 + t];
                  smf[SB2 + 128 + t] = b2g[128 + t]; smf[SB2 + 192 + t] = b2g[192 + t];
                  smf[SB3 + t] = b3g[t]; }
    __syncthreads();

    const int lane = t & 31;
    const int gq = lane >> 2, tig = lane & 3;
    const int warp = blockIdx.x * (NTHR / 32) + (t >> 5);

    for (int grp = warp; grp < NGROUP; grp += NWARPS) {
        int base = grp * 16;
        int p0 = base + gq, p1 = p0 + 8;
        float x00 = pt_fea[p0 * 3], x01 = pt_fea[p0 * 3 + 1], x02 = pt_fea[p0 * 3 + 2];
        float x10 = pt_fea[p1 * 3], x11 = pt_fea[p1 * 3 + 1], x12 = pt_fea[p1 * 3 + 2];
        int2 v0 = ((const int2*)xy)[p0];
        int2 v1 = ((const int2*)xy)[p1];
        int r0 = g_rank[((p0 / NPTS) * GRIDW + v0.x) * GRIDW + v0.y];
        int r1 = g_rank[((p1 / NPTS) * GRIDW + v1.x) * GRIDW + v1.y];

        // ---- layer 1 -> fp16 A fragments (m16k16): A[ks][0..3] ----
        uint32_t A[8][4];
        #pragma unroll
        for (int ks = 0; ks < 8; ks++) {
            int c0 = ks * 16 + tig * 2;
            int c8 = c0 + 8;
            #pragma unroll
            for (int h = 0; h < 2; h++) {
                int c = h ? c8 : c0;
                float wa0 = smf[SW1 + c],       wa1 = smf[SW1 + c + 1];
                float wb0 = smf[SW1 + 128 + c], wb1 = smf[SW1 + 128 + c + 1];
                float wc0 = smf[SW1 + 256 + c], wc1 = smf[SW1 + 256 + c + 1];
                float ba = smf[SB1 + c], bb = smf[SB1 + c + 1];
                float p0a = fmaxf(fmaf(x02, wc0, fmaf(x01, wb0, fmaf(x00, wa0, ba))), 0.f);
                float p0b = fmaxf(fmaf(x02, wc1, fmaf(x01, wb1, fmaf(x00, wa1, bb))), 0.f);
                float p1a = fmaxf(fmaf(x12, wc0, fmaf(x11, wb0, fmaf(x10, wa0, ba))), 0.f);
                float p1b = fmaxf(fmaf(x12, wc1, fmaf(x11, wb1, fmaf(x10, wa1, bb))), 0.f);
                A[ks][0 + h * 2] = f2h2(p0a, p0b);
                A[ks][1 + h * 2] = f2h2(p1a, p1b);
            }
        }

        float acc3[8][4];
        #pragma unroll
        for (int n = 0; n < 8; n++)
            #pragma unroll
            for (int q = 0; q < 4; q++) acc3[n][q] = 0.f;

        #pragma unroll 1
        for (int nc = 0; nc < 4; nc++) {
            const uint32_t* w2p = sm + SW2 + nc * 4096 + lane * 2;
            const uint32_t* w3p = sm + SW3 + nc * 2048 + lane * 2;
            // nt-pair outer: acc2 lives only within one pair (8 regs)
            #pragma unroll
            for (int kt = 0; kt < 4; kt++) {
                int ntA = 2 * kt, ntB = 2 * kt + 1;
                float accA[4] = {0.f, 0.f, 0.f, 0.f};
                float accB[4] = {0.f, 0.f, 0.f, 0.f};
                #pragma unroll
                for (int ks = 0; ks < 8; ks++) {
                    uint2 bA = *(const uint2*)(w2p + (ks * 8 + ntA) * 64);
                    mma16(accA, A[ks], bA.x, bA.y);
                    uint2 bB = *(const uint2*)(w2p + (ks * 8 + ntB) * 64);
                    mma16(accB, A[ks], bB.x, bB.y);
                }
                float bA0 = smf[SB2 + nc * 64 + ntA * 8 + 2 * tig];
                float bA1 = smf[SB2 + nc * 64 + ntA * 8 + 2 * tig + 1];
                float bB0 = smf[SB2 + nc * 64 + ntB * 8 + 2 * tig];
                float bB1 = smf[SB2 + nc * 64 + ntB * 8 + 2 * tig + 1];
                uint32_t af[4];
                af[0] = f2h2(fmaxf(accA[0] + bA0, 0.f), fmaxf(accA[1] + bA1, 0.f));
                af[1] = f2h2(fmaxf(accA[2] + bA0, 0.f), fmaxf(accA[3] + bA1, 0.f));
                af[2] = f2h2(fmaxf(accB[0] + bB0, 0.f), fmaxf(accB[1] + bB1, 0.f));
                af[3] = f2h2(fmaxf(accB[2] + bB0, 0.f), fmaxf(accB[3] + bB1, 0.f));
                #pragma unroll
                for (int nt3 = 0; nt3 < 8; nt3++) {
                    uint2 b = *(const uint2*)(w3p + (kt * 8 + nt3) * 64);
                    mma16(acc3[nt3], af, b.x, b.y);
                }
            }
        }

        // ---- epilogue: +b3; solo fast STG, else sign-split atomics ----
        #pragma unroll
        for (int half = 0; half < 2; half++) {
            int r = half ? r1 : r0;
            size_t rb = (size_t)(r >> 1) * 64;
            if (r & 1) {
                float* dst = pooled + rb;
                #pragma unroll
                for (int nt3 = 0; nt3 < 8; nt3++) {
                    int col = nt3 * 8 + 2 * tig;
                    float2 val;
                    val.x = acc3[nt3][2 * half]     + smf[SB3 + col];
                    val.y = acc3[nt3][2 * half + 1] + smf[SB3 + col + 1];
                    *(float2*)(dst + col) = val;
                }
            } else {
                float* dst = pooled + rb;
                #pragma unroll
                for (int nt3 = 0; nt3 < 8; nt3++) {
                    int col = nt3 * 8 + 2 * tig;
                    atomic_fmax(dst + col,     acc3[nt3][2 * half]     + smf[SB3 + col]);
                    atomic_fmax(dst + col + 1, acc3[nt3][2 * half + 1] + smf[SB3 + col + 1]);
                }
            }
        }
    }
}

// ---------------- host launcher ----------------
extern "C" void kernel_launch(void* const* d_in, const int* in_sizes, int n_in,
                              void* d_out, int out_size) {
    const float* pt_fea = (const float*)d_in[0];
    const int*   xy     = (const int*)d_in[1];
    const float* W1     = (const float*)d_in[2];
    const float* b1     = (const float*)d_in[3];
    const float* W2     = (const float*)d_in[4];
    const float* b2     = (const float*)d_in[5];
    const float* W3     = (const float*)d_in[6];
    const float* b3     = (const float*)d_in[7];

    int M;
    float* unq_out;
    float* pooled;
    if (out_size % 67 == 0) {
        M = out_size / 67;
        unq_out = (float*)d_out;
        pooled = (float*)d_out + (size_t)3 * M;
    } else {
        M = out_size / 64;
        unq_out = nullptr;
        pooled = (float*)d_out;
    }

    cudaFuncSetAttribute(k_mlp, cudaFuncAttributeMaxDynamicSharedMemorySize, SMEM_BYTES);

    k_mark<<<(PTOT + 255) / 256, 256>>>(xy);
    k_scan1<<<NCELL / 1024, 1024>>>();
    k_scan3<<<NCELL / 1024, 1024>>>(unq_out, (uint2*)pooled);
    k_mlp<<<NSM, NTHR, SMEM_BYTES>>>(pt_fea, xy, W1, b1, W2, b2, W3, b3, pooled);
}

// round 11
// speedup vs baseline: 1.0538x; 1.0002x over previous
#include <cuda_runtime.h>
#include <cstdint>

#define GRIDW 480
#define NPTS 100000
#define PTOT 400000
#define NCELL (4*GRIDW*GRIDW)      // 921600
#define NSM 148
#define NTHR 384
#define NWARPS (NSM*12)            // 1776
#define NGROUP (PTOT/16)           // 25000 warp-tiles of 16 points

// ---------------- smem layout (u32 offsets) ----------------
#define SW2 0        // W2 B-frags fp16: 4nc x 8ks x 8nt x 64 = 16384 u32
#define SW3 16384    // W3 B-frags fp16: 4nc x 4kt x 8nt x 64 = 8192 u32
#define SW1 24576    // 3*128 f32
#define SB1 24960    // 128
#define SB2 25088    // 256
#define SB3 25344    // 64
#define SMEM_U32 25408
#define SMEM_BYTES (SMEM_U32*4)    // 101632 B

// ---------------- device scratch ----------------
__device__ int g_cnt[NCELL];      // zero at load; self-resetting (scan1 clears)
__device__ int g_rank[NCELL];     // scan1: partial|flags ; scan3: (rank<<1)|solo
__device__ int g_bsum[1024];

// ---------------- helpers ----------------
__device__ __forceinline__ uint32_t f2h2(float lo, float hi) {
    uint32_t r;
    asm("cvt.rn.f16x2.f32 %0, %1, %2;" : "=r"(r) : "f"(hi), "f"(lo));
    return r;
}
__device__ __forceinline__ unsigned short f2h(float f) {
    unsigned short h;
    asm("cvt.rn.f16.f32 %0, %1;" : "=h"(h) : "f"(f));
    return h;
}
__device__ __forceinline__ void mma16(float* d, const uint32_t* a, uint32_t b0, uint32_t b1) {
    asm volatile("mma.sync.aligned.m16n8k16.row.col.f32.f16.f16.f32 "
        "{%0,%1,%2,%3},{%4,%5,%6,%7},{%8,%9},{%0,%1,%2,%3};"
        : "+f"(d[0]), "+f"(d[1]), "+f"(d[2]), "+f"(d[3])
        : "r"(a[0]), "r"(a[1]), "r"(a[2]), "r"(a[3]), "r"(b0), "r"(b1));
}
__device__ __forceinline__ void atomic_fmax(float* addr, float v) {
    if (v >= 0.0f) atomicMax((int*)addr, __float_as_int(v));
    else atomicMin((unsigned int*)addr, __float_as_uint(v));
}

// ---------------- small kernels ----------------
__global__ void k_mark(const int* __restrict__ xy) {
    int p = blockIdx.x * blockDim.x + threadIdx.x;
    if (p < PTOT) {
        int2 v = ((const int2*)xy)[p];
        int b = p / NPTS;
        atomicAdd(&g_cnt[(b * GRIDW + v.x) * GRIDW + v.y], 1);
    }
}

// per-block exclusive scan of occupancy; packs occ/solo flags; zeroes g_cnt for next replay
__global__ void k_scan1() {
    __shared__ int ws[32];
    int i = blockIdx.x * 1024 + threadIdx.x;
    int lane = threadIdx.x & 31, wid = threadIdx.x >> 5;
    int c = g_cnt[i];
    if (c) g_cnt[i] = 0;                    // self-reset (write only if dirty)
    int v = (c != 0);
    unsigned int m = __ballot_sync(0xffffffffu, v);
    int excl = __popc(m & ((1u << lane) - 1u));
    if (lane == 31) ws[wid] = excl + v;
    __syncthreads();
    if (wid == 0) {
        int x = ws[lane];
        #pragma unroll
        for (int d = 1; d < 32; d <<= 1) {
            int o = __shfl_up_sync(0xffffffffu, x, d);
            if (lane >= d) x += o;
        }
        ws[lane] = x;
    }
    __syncthreads();
    int partial = excl + (wid ? ws[wid - 1] : 0);
    g_rank[i] = partial | (v << 16) | ((c == 1) << 17);
    if (threadIdx.x == 1023) g_bsum[blockIdx.x] = ws[31];
}

// finalize ranks (block offset computed inline from g_bsum), write unq rows,
// and -inf-init pooled rows of non-solo voxels (warp-cooperative, coalesced).
__global__ void k_scan3(float* unq_out, uint2* pooled) {
    __shared__ int ws[32];
    __shared__ int s_off;
    int t = threadIdx.x;
    int lane = t & 31, wid = t >> 5;

    int v = (t < blockIdx.x && t < 900) ? g_bsum[t] : 0;
    #pragma unroll
    for (int d = 16; d > 0; d >>= 1)
        v += __shfl_xor_sync(0xffffffffu, v, d);
    if (lane == 0) ws[wid] = v;
    __syncthreads();
    if (wid == 0) {
        int x = ws[lane];
        #pragma unroll
        for (int d = 16; d > 0; d >>= 1)
            x += __shfl_xor_sync(0xffffffffu, x, d);
        if (lane == 0) s_off = x;
    }
    __syncthreads();
    int off = s_off;

    int i = blockIdx.x * 1024 + t;
    int packed = g_rank[i];
    int occ = (packed >> 16) & 1;
    int solo = (packed >> 17) & 1;
    int r = (packed & 0xFFFF) + off;
    if (occ) {
        g_rank[i] = (r << 1) | solo;
        if (unq_out) {
            int b = i / (GRIDW * GRIDW);
            int rem = i - b * GRIDW * GRIDW;
            unq_out[3 * r + 0] = (float)b;
            unq_out[3 * r + 1] = (float)(rem / GRIDW);
            unq_out[3 * r + 2] = (float)(rem % GRIDW);
        }
    }
    unsigned int nm = __ballot_sync(0xffffffffu, occ && !solo);
    uint2 ninf = make_uint2(0xff800000u, 0xff800000u);
    while (nm) {
        int src = __ffs(nm) - 1;
        nm &= nm - 1;
        int rr = __shfl_sync(0xffffffffu, r, src);
        pooled[(size_t)rr * 32 + lane] = ninf;
    }
}

// ---------------- fused fp16 mma.sync MLP, M=16/warp, prefetched inputs, 4 acc chains ----
__global__ void __launch_bounds__(NTHR, 1)
k_mlp(const float* __restrict__ pt_fea, const int* __restrict__ xy,
      const float* __restrict__ W1g, const float* __restrict__ b1g,
      const float* __restrict__ W2g, const float* __restrict__ b2g,
      const float* __restrict__ W3g, const float* __restrict__ b3g,
      float* __restrict__ pooled) {
    extern __shared__ uint32_t sm[];
    float* smf = (float*)sm;
    int t = threadIdx.x;

    // ---- stage W2 as fp16 B-frags: sm[SW2 + ((nc*8+ks)*8+nt)*64 + lane*2 + j] ----
    for (int idx = t; idx < 16384; idx += NTHR) {
        int j = idx & 1, lane = (idx >> 1) & 31, nt = (idx >> 6) & 7,
            ks = (idx >> 9) & 7, nc = idx >> 12;
        int k = ks * 16 + (lane & 3) * 2 + j * 8;
        int n = nc * 64 + nt * 8 + (lane >> 2);
        sm[SW2 + idx] = (uint32_t)f2h(W2g[k * 256 + n]) |
                        ((uint32_t)f2h(W2g[(k + 1) * 256 + n]) << 16);
    }
    // ---- stage W3 as fp16 B-frags: sm[SW3 + ((nc*4+kt)*8+nt)*64 + lane*2 + j] ----
    for (int idx = t; idx < 8192; idx += NTHR) {
        int j = idx & 1, lane = (idx >> 1) & 31, nt = (idx >> 6) & 7,
            kt = (idx >> 9) & 3, nc = idx >> 11;
        int k = nc * 64 + kt * 16 + (lane & 3) * 2 + j * 8;
        int n = nt * 8 + (lane >> 2);
        sm[SW3 + idx] = (uint32_t)f2h(W3g[k * 64 + n]) |
                        ((uint32_t)f2h(W3g[(k + 1) * 64 + n]) << 16);
    }
    for (int i = t; i < 384; i += NTHR) smf[SW1 + i] = W1g[i];
    if (t < 128) smf[SB1 + t] = b1g[t];
    if (t < 64) { smf[SB2 + t] = b2g[t]; smf[SB2 + 64 + t] = b2g[64 + t];
                  smf[SB2 + 128 + t] = b2g[128 + t]; smf[SB2 + 192 + t] = b2g[192 + t];
                  smf[SB3 + t] = b3g[t]; }
    __syncthreads();

    const int lane = t & 31;
    const int gq = lane >> 2, tig = lane & 3;
    const int warp = blockIdx.x * (NTHR / 32) + (t >> 5);
    const int2* __restrict__ xy2 = (const int2*)xy;

    // ---- prologue: load inputs for the first tile ----
    int grp = warp;
    int p0 = grp * 16 + gq, p1 = p0 + 8;
    int2 v0 = xy2[p0], v1 = xy2[p1];
    float x00 = pt_fea[p0 * 3], x01 = pt_fea[p0 * 3 + 1], x02 = pt_fea[p0 * 3 + 2];
    float x10 = pt_fea[p1 * 3], x11 = pt_fea[p1 * 3 + 1], x12 = pt_fea[p1 * 3 + 2];
    int r0 = g_rank[((p0 / NPTS) * GRIDW + v0.x) * GRIDW + v0.y];
    int r1 = g_rank[((p1 / NPTS) * GRIDW + v1.x) * GRIDW + v1.y];

    #pragma unroll 1
    while (grp < NGROUP) {
        // ---- prefetch next tile's xy + pt_fea (hidden under this tile's compute) ----
        int ngrp = grp + NWARPS;
        bool more = ngrp < NGROUP;
        int q0 = ngrp * 16 + gq, q1 = q0 + 8;
        int2 nv0, nv1;
        float nx00, nx01, nx02, nx10, nx11, nx12;
        int nr0 = 0, nr1 = 0;
        if (more) {
            nv0 = xy2[q0]; nv1 = xy2[q1];
            nx00 = pt_fea[q0 * 3]; nx01 = pt_fea[q0 * 3 + 1]; nx02 = pt_fea[q0 * 3 + 2];
            nx10 = pt_fea[q1 * 3]; nx11 = pt_fea[q1 * 3 + 1]; nx12 = pt_fea[q1 * 3 + 2];
        }

        // ---- layer 1 -> fp16 A fragments (m16k16): A[ks][0..3] ----
        uint32_t A[8][4];
        #pragma unroll
        for (int ks = 0; ks < 8; ks++) {
            int c0 = ks * 16 + tig * 2;
            int c8 = c0 + 8;
            #pragma unroll
            for (int h = 0; h < 2; h++) {
                int c = h ? c8 : c0;
                float wa0 = smf[SW1 + c],       wa1 = smf[SW1 + c + 1];
                float wb0 = smf[SW1 + 128 + c], wb1 = smf[SW1 + 128 + c + 1];
                float wc0 = smf[SW1 + 256 + c], wc1 = smf[SW1 + 256 + c + 1];
                float ba = smf[SB1 + c], bb = smf[SB1 + c + 1];
                float p0a = fmaxf(fmaf(x02, wc0, fmaf(x01, wb0, fmaf(x00, wa0, ba))), 0.f);
                float p0b = fmaxf(fmaf(x02, wc1, fmaf(x01, wb1, fmaf(x00, wa1, bb))), 0.f);
                float p1a = fmaxf(fmaf(x12, wc0, fmaf(x11, wb0, fmaf(x10, wa0, ba))), 0.f);
                float p1b = fmaxf(fmaf(x12, wc1, fmaf(x11, wb1, fmaf(x10, wa1, bb))), 0.f);
                A[ks][0 + h * 2] = f2h2(p0a, p0b);
                A[ks][1 + h * 2] = f2h2(p1a, p1b);
            }
        }

        // ---- prefetch next tile's ranks (depends on nv0/nv1, now ~600cyc old) ----
        if (more) {
            nr0 = g_rank[((q0 / NPTS) * GRIDW + nv0.x) * GRIDW + nv0.y];
            nr1 = g_rank[((q1 / NPTS) * GRIDW + nv1.x) * GRIDW + nv1.y];
        }

        float acc3[8][4];
        #pragma unroll
        for (int n = 0; n < 8; n++)
            #pragma unroll
            for (int q = 0; q < 4; q++) acc3[n][q] = 0.f;

        #pragma unroll 1
        for (int nc = 0; nc < 4; nc++) {
            const uint32_t* w2p = sm + SW2 + nc * 4096 + lane * 2;
            const uint32_t* w3p = sm + SW3 + nc * 2048 + lane * 2;
            #pragma unroll
            for (int kt = 0; kt < 4; kt++) {
                int ntA = 2 * kt, ntB = 2 * kt + 1;
                // 4 independent accumulator chains (even/odd ks split) to halve
                // the dependent-HMMA critical path; merged below.
                float accA[4] = {0.f, 0.f, 0.f, 0.f};
                float accAo[4] = {0.f, 0.f, 0.f, 0.f};
                float accB[4] = {0.f, 0.f, 0.f, 0.f};
                float accBo[4] = {0.f, 0.f, 0.f, 0.f};
                #pragma unroll
                for (int ks2 = 0; ks2 < 4; ks2++) {
                    int ksE = 2 * ks2, ksO = 2 * ks2 + 1;
                    uint2 bAE = *(const uint2*)(w2p + (ksE * 8 + ntA) * 64);
                    mma16(accA, A[ksE], bAE.x, bAE.y);
                    uint2 bAO = *(const uint2*)(w2p + (ksO * 8 + ntA) * 64);
                    mma16(accAo, A[ksO], bAO.x, bAO.y);
                    uint2 bBE = *(const uint2*)(w2p + (ksE * 8 + ntB) * 64);
                    mma16(accB, A[ksE], bBE.x, bBE.y);
                    uint2 bBO = *(const uint2*)(w2p + (ksO * 8 + ntB) * 64);
                    mma16(accBo, A[ksO], bBO.x, bBO.y);
                }
                #pragma unroll
                for (int q = 0; q < 4; q++) {
                    accA[q] += accAo[q];
                    accB[q] += accBo[q];
                }
                float bA0 = smf[SB2 + nc * 64 + ntA * 8 + 2 * tig];
                float bA1 = smf[SB2 + nc * 64 + ntA * 8 + 2 * tig + 1];
                float bB0 = smf[SB2 + nc * 64 + ntB * 8 + 2 * tig];
                float bB1 = smf[SB2 + nc * 64 + ntB * 8 + 2 * tig + 1];
                uint32_t af[4];
                af[0] = f2h2(fmaxf(accA[0] + bA0, 0.f), fmaxf(accA[1] + bA1, 0.f));
                af[1] = f2h2(fmaxf(accA[2] + bA0, 0.f), fmaxf(accA[3] + bA1, 0.f));
                af[2] = f2h2(fmaxf(accB[0] + bB0, 0.f), fmaxf(accB[1] + bB1, 0.f));
                af[3] = f2h2(fmaxf(accB[2] + bB0, 0.f), fmaxf(accB[3] + bB1, 0.f));
                #pragma unroll
                for (int nt3 = 0; nt3 < 8; nt3++) {
                    uint2 b = *(const uint2*)(w3p + (kt * 8 + nt3) * 64);
                    mma16(acc3[nt3], af, b.x, b.y);
                }
            }
        }

        // ---- epilogue: +b3; solo fast STG, else sign-split atomics ----
        #pragma unroll
        for (int half = 0; half < 2; half++) {
            int r = half ? r1 : r0;
            size_t rb = (size_t)(r >> 1) * 64;
            if (r & 1) {
                float* dst = pooled + rb;
                #pragma unroll
                for (int nt3 = 0; nt3 < 8; nt3++) {
                    int col = nt3 * 8 + 2 * tig;
                    float2 val;
                    val.x = acc3[nt3][2 * half]     + smf[SB3 + col];
                    val.y = acc3[nt3][2 * half + 1] + smf[SB3 + col + 1];
                    *(float2*)(dst + col) = val;
                }
            } else {
                float* dst = pooled + rb;
                #pragma unroll
                for (int nt3 = 0; nt3 < 8; nt3++) {
                    int col = nt3 * 8 + 2 * tig;
                    atomic_fmax(dst + col,     acc3[nt3][2 * half]     + smf[SB3 + col]);
                    atomic_fmax(dst + col + 1, acc3[nt3][2 * half + 1] + smf[SB3 + col + 1]);
                }
            }
        }

        // ---- rotate prefetched state ----
        grp = ngrp;
        if (more) {
            v0 = nv0; v1 = nv1;
            x00 = nx00; x01 = nx01; x02 = nx02;
            x10 = nx10; x11 = nx11; x12 = nx12;
            r0 = nr0; r1 = nr1;
        }
    }
}

// ---------------- host launcher ----------------
extern "C" void kernel_launch(void* const* d_in, const int* in_sizes, int n_in,
                              void* d_out, int out_size) {
    const float* pt_fea = (const float*)d_in[0];
    const int*   xy     = (const int*)d_in[1];
    const float* W1     = (const float*)d_in[2];
    const float* b1     = (const float*)d_in[3];
    const float* W2     = (const float*)d_in[4];
    const float* b2     = (const float*)d_in[5];
    const float* W3     = (const float*)d_in[6];
    const float* b3     = (const float*)d_in[7];

    int M;
    float* unq_out;
    float* pooled;
    if (out_size % 67 == 0) {
        M = out_size / 67;
        unq_out = (float*)d_out;
        pooled = (float*)d_out + (size_t)3 * M;
    } else {
        M = out_size / 64;
        unq_out = nullptr;
        pooled = (float*)d_out;
    }

    cudaFuncSetAttribute(k_mlp, cudaFuncAttributeMaxDynamicSharedMemorySize, SMEM_BYTES);

    k_mark<<<(PTOT + 255) / 256, 256>>>(xy);
    k_scan1<<<NCELL / 1024, 1024>>>();
    k_scan3<<<NCELL / 1024, 1024>>>(unq_out, (uint2*)pooled);
    k_mlp<<<NSM, NTHR, SMEM_BYTES>>>(pt_fea, xy, W1, b1, W2, b2, W3, b3, pooled);
}

// round 12
// speedup vs baseline: 1.0944x; 1.0385x over previous
#include <cuda_runtime.h>
#include <cstdint>

#define GRIDW 480
#define NPTS 100000
#define PTOT 400000
#define NCELL (4*GRIDW*GRIDW)      // 921600
#define NSM 148
#define NTHR 512
#define NWARPS (NSM*16)            // 2368
#define NGROUP (PTOT/16)           // 25000 warp-tiles of 16 points

// ---------------- smem layout (u32 offsets) ----------------
#define SW2 0        // W2 B-frags fp16: 4nc x 8ks x 8nt x 64 = 16384 u32
#define SW3 16384    // W3 B-frags fp16: 4nc x 4kt x 8nt x 64 = 8192 u32
#define SW1 24576    // 3*128 f32
#define SB1 24960    // 128
#define SB2 25088    // 256
#define SB3 25344    // 64
#define SMEM_U32 25408
#define SMEM_BYTES (SMEM_U32*4)    // 101632 B

// ---------------- device scratch ----------------
__device__ int g_cnt[NCELL];      // zero at load; self-resetting (scan1 clears)
__device__ int g_rank[NCELL];     // scan1: partial|flags ; scan3: (rank<<1)|solo
__device__ int g_bsum[1024];

// ---------------- helpers ----------------
__device__ __forceinline__ uint32_t f2h2(float lo, float hi) {
    uint32_t r;
    asm("cvt.rn.f16x2.f32 %0, %1, %2;" : "=r"(r) : "f"(hi), "f"(lo));
    return r;
}
__device__ __forceinline__ unsigned short f2h(float f) {
    unsigned short h;
    asm("cvt.rn.f16.f32 %0, %1;" : "=h"(h) : "f"(f));
    return h;
}
__device__ __forceinline__ void mma16(float* d, const uint32_t* a, uint32_t b0, uint32_t b1) {
    asm volatile("mma.sync.aligned.m16n8k16.row.col.f32.f16.f16.f32 "
        "{%0,%1,%2,%3},{%4,%5,%6,%7},{%8,%9},{%0,%1,%2,%3};"
        : "+f"(d[0]), "+f"(d[1]), "+f"(d[2]), "+f"(d[3])
        : "r"(a[0]), "r"(a[1]), "r"(a[2]), "r"(a[3]), "r"(b0), "r"(b1));
}
__device__ __forceinline__ void atomic_fmax(float* addr, float v) {
    if (v >= 0.0f) atomicMax((int*)addr, __float_as_int(v));
    else atomicMin((unsigned int*)addr, __float_as_uint(v));
}

// ---------------- small kernels ----------------
__global__ void k_mark(const int* __restrict__ xy) {
    int p = blockIdx.x * blockDim.x + threadIdx.x;
    if (p < PTOT) {
        int2 v = ((const int2*)xy)[p];
        int b = p / NPTS;
        atomicAdd(&g_cnt[(b * GRIDW + v.x) * GRIDW + v.y], 1);
    }
}

// per-block exclusive scan of occupancy; packs occ/solo flags; zeroes g_cnt for next replay
__global__ void k_scan1() {
    __shared__ int ws[32];
    int i = blockIdx.x * 1024 + threadIdx.x;
    int lane = threadIdx.x & 31, wid = threadIdx.x >> 5;
    int c = g_cnt[i];
    if (c) g_cnt[i] = 0;                    // self-reset (write only if dirty)
    int v = (c != 0);
    unsigned int m = __ballot_sync(0xffffffffu, v);
    int excl = __popc(m & ((1u << lane) - 1u));
    if (lane == 31) ws[wid] = excl + v;
    __syncthreads();
    if (wid == 0) {
        int x = ws[lane];
        #pragma unroll
        for (int d = 1; d < 32; d <<= 1) {
            int o = __shfl_up_sync(0xffffffffu, x, d);
            if (lane >= d) x += o;
        }
        ws[lane] = x;
    }
    __syncthreads();
    int partial = excl + (wid ? ws[wid - 1] : 0);
    g_rank[i] = partial | (v << 16) | ((c == 1) << 17);
    if (threadIdx.x == 1023) g_bsum[blockIdx.x] = ws[31];
}

// finalize ranks (block offset computed inline from g_bsum), write unq rows,
// and -inf-init pooled rows of non-solo voxels (warp-cooperative, coalesced).
__global__ void k_scan3(float* unq_out, uint2* pooled) {
    __shared__ int ws[32];
    __shared__ int s_off;
    int t = threadIdx.x;
    int lane = t & 31, wid = t >> 5;

    int v = (t < blockIdx.x && t < 900) ? g_bsum[t] : 0;
    #pragma unroll
    for (int d = 16; d > 0; d >>= 1)
        v += __shfl_xor_sync(0xffffffffu, v, d);
    if (lane == 0) ws[wid] = v;
    __syncthreads();
    if (wid == 0) {
        int x = ws[lane];
        #pragma unroll
        for (int d = 16; d > 0; d >>= 1)
            x += __shfl_xor_sync(0xffffffffu, x, d);
        if (lane == 0) s_off = x;
    }
    __syncthreads();
    int off = s_off;

    int i = blockIdx.x * 1024 + t;
    int packed = g_rank[i];
    int occ = (packed >> 16) & 1;
    int solo = (packed >> 17) & 1;
    int r = (packed & 0xFFFF) + off;
    if (occ) {
        g_rank[i] = (r << 1) | solo;
        if (unq_out) {
            int b = i / (GRIDW * GRIDW);
            int rem = i - b * GRIDW * GRIDW;
            unq_out[3 * r + 0] = (float)b;
            unq_out[3 * r + 1] = (float)(rem / GRIDW);
            unq_out[3 * r + 2] = (float)(rem % GRIDW);
        }
    }
    unsigned int nm = __ballot_sync(0xffffffffu, occ && !solo);
    uint2 ninf = make_uint2(0xff800000u, 0xff800000u);
    while (nm) {
        int src = __ffs(nm) - 1;
        nm &= nm - 1;
        int rr = __shfl_sync(0xffffffffu, r, src);
        pooled[(size_t)rr * 32 + lane] = ninf;
    }
}

// ---------------- fused fp16 mma.sync MLP, M=16/warp, 16 warps, xy/rank prefetch ----
__global__ void __launch_bounds__(NTHR, 1)
k_mlp(const float* __restrict__ pt_fea, const int* __restrict__ xy,
      const float* __restrict__ W1g, const float* __restrict__ b1g,
      const float* __restrict__ W2g, const float* __restrict__ b2g,
      const float* __restrict__ W3g, const float* __restrict__ b3g,
      float* __restrict__ pooled) {
    extern __shared__ uint32_t sm[];
    float* smf = (float*)sm;
    int t = threadIdx.x;

    // ---- stage W2 as fp16 B-frags: sm[SW2 + ((nc*8+ks)*8+nt)*64 + lane*2 + j] ----
    for (int idx = t; idx < 16384; idx += NTHR) {
        int j = idx & 1, lane = (idx >> 1) & 31, nt = (idx >> 6) & 7,
            ks = (idx >> 9) & 7, nc = idx >> 12;
        int k = ks * 16 + (lane & 3) * 2 + j * 8;
        int n = nc * 64 + nt * 8 + (lane >> 2);
        sm[SW2 + idx] = (uint32_t)f2h(W2g[k * 256 + n]) |
                        ((uint32_t)f2h(W2g[(k + 1) * 256 + n]) << 16);
    }
    // ---- stage W3 as fp16 B-frags: sm[SW3 + ((nc*4+kt)*8+nt)*64 + lane*2 + j] ----
    for (int idx = t; idx < 8192; idx += NTHR) {
        int j = idx & 1, lane = (idx >> 1) & 31, nt = (idx >> 6) & 7,
            kt = (idx >> 9) & 3, nc = idx >> 11;
        int k = nc * 64 + kt * 16 + (lane & 3) * 2 + j * 8;
        int n = nt * 8 + (lane >> 2);
        sm[SW3 + idx] = (uint32_t)f2h(W3g[k * 64 + n]) |
                        ((uint32_t)f2h(W3g[(k + 1) * 64 + n]) << 16);
    }
    for (int i = t; i < 384; i += NTHR) smf[SW1 + i] = W1g[i];
    if (t < 128) smf[SB1 + t] = b1g[t];
    if (t < 64) { smf[SB2 + t] = b2g[t]; smf[SB2 + 64 + t] = b2g[64 + t];
                  smf[SB2 + 128 + t] = b2g[128 + t]; smf[SB2 + 192 + t] = b2g[192 + t];
                  smf[SB3 + t] = b3g[t]; }
    __syncthreads();

    const int lane = t & 31;
    const int gq = lane >> 2, tig = lane & 3;
    const int warp = blockIdx.x * (NTHR / 32) + (t >> 5);
    const int2* __restrict__ xy2 = (const int2*)xy;

    // ---- prologue: resolve first tile's rank chain up front ----
    int grp = warp;
    int r0 = 0, r1 = 0;
    {
        int p0 = grp * 16 + gq, p1 = p0 + 8;
        int2 v0 = xy2[p0], v1 = xy2[p1];
        r0 = g_rank[((p0 / NPTS) * GRIDW + v0.x) * GRIDW + v0.y];
        r1 = g_rank[((p1 / NPTS) * GRIDW + v1.x) * GRIDW + v1.y];
    }

    #pragma unroll 1
    while (grp < NGROUP) {
        int p0 = grp * 16 + gq, p1 = p0 + 8;
        float x00 = pt_fea[p0 * 3], x01 = pt_fea[p0 * 3 + 1], x02 = pt_fea[p0 * 3 + 2];
        float x10 = pt_fea[p1 * 3], x11 = pt_fea[p1 * 3 + 1], x12 = pt_fea[p1 * 3 + 2];

        // prefetch next tile's xy (first link of the rank chain)
        int ngrp = grp + NWARPS;
        bool more = ngrp < NGROUP;
        int2 nv0, nv1;
        if (more) {
            int q0 = ngrp * 16 + gq;
            nv0 = xy2[q0]; nv1 = xy2[q0 + 8];
        }

        // ---- layer 1 -> fp16 A fragments (m16k16): A[ks][0..3] ----
        uint32_t A[8][4];
        #pragma unroll
        for (int ks = 0; ks < 8; ks++) {
            int c0 = ks * 16 + tig * 2;
            int c8 = c0 + 8;
            #pragma unroll
            for (int h = 0; h < 2; h++) {
                int c = h ? c8 : c0;
                float wa0 = smf[SW1 + c],       wa1 = smf[SW1 + c + 1];
                float wb0 = smf[SW1 + 128 + c], wb1 = smf[SW1 + 128 + c + 1];
                float wc0 = smf[SW1 + 256 + c], wc1 = smf[SW1 + 256 + c + 1];
                float ba = smf[SB1 + c], bb = smf[SB1 + c + 1];
                float p0a = fmaxf(fmaf(x02, wc0, fmaf(x01, wb0, fmaf(x00, wa0, ba))), 0.f);
                float p0b = fmaxf(fmaf(x02, wc1, fmaf(x01, wb1, fmaf(x00, wa1, bb))), 0.f);
                float p1a = fmaxf(fmaf(x12, wc0, fmaf(x11, wb0, fmaf(x10, wa0, ba))), 0.f);
                float p1b = fmaxf(fmaf(x12, wc1, fmaf(x11, wb1, fmaf(x10, wa1, bb))), 0.f);
                A[ks][0 + h * 2] = f2h2(p0a, p0b);
                A[ks][1 + h * 2] = f2h2(p1a, p1b);
            }
        }

        // prefetch next tile's ranks (second link; xy arrived during layer 1)
        int nr0 = 0, nr1 = 0;
        if (more) {
            int q0 = ngrp * 16 + gq, q1 = q0 + 8;
            nr0 = g_rank[((q0 / NPTS) * GRIDW + nv0.x) * GRIDW + nv0.y];
            nr1 = g_rank[((q1 / NPTS) * GRIDW + nv1.x) * GRIDW + nv1.y];
        }

        float acc3[8][4];
        #pragma unroll
        for (int n = 0; n < 8; n++)
            #pragma unroll
            for (int q = 0; q < 4; q++) acc3[n][q] = 0.f;

        #pragma unroll 1
        for (int nc = 0; nc < 4; nc++) {
            const uint32_t* w2p = sm + SW2 + nc * 4096 + lane * 2;
            const uint32_t* w3p = sm + SW3 + nc * 2048 + lane * 2;
            // nt-pair outer: acc2 lives only within one pair (8 regs)
            #pragma unroll
            for (int kt = 0; kt < 4; kt++) {
                int ntA = 2 * kt, ntB = 2 * kt + 1;
                float accA[4] = {0.f, 0.f, 0.f, 0.f};
                float accB[4] = {0.f, 0.f, 0.f, 0.f};
                #pragma unroll
                for (int ks = 0; ks < 8; ks++) {
                    uint2 bA = *(const uint2*)(w2p + (ks * 8 + ntA) * 64);
                    mma16(accA, A[ks], bA.x, bA.y);
                    uint2 bB = *(const uint2*)(w2p + (ks * 8 + ntB) * 64);
                    mma16(accB, A[ks], bB.x, bB.y);
                }
                float bA0 = smf[SB2 + nc * 64 + ntA * 8 + 2 * tig];
                float bA1 = smf[SB2 + nc * 64 + ntA * 8 + 2 * tig + 1];
                float bB0 = smf[SB2 + nc * 64 + ntB * 8 + 2 * tig];
                float bB1 = smf[SB2 + nc * 64 + ntB * 8 + 2 * tig + 1];
                uint32_t af[4];
                af[0] = f2h2(fmaxf(accA[0] + bA0, 0.f), fmaxf(accA[1] + bA1, 0.f));
                af[1] = f2h2(fmaxf(accA[2] + bA0, 0.f), fmaxf(accA[3] + bA1, 0.f));
                af[2] = f2h2(fmaxf(accB[0] + bB0, 0.f), fmaxf(accB[1] + bB1, 0.f));
                af[3] = f2h2(fmaxf(accB[2] + bB0, 0.f), fmaxf(accB[3] + bB1, 0.f));
                #pragma unroll
                for (int nt3 = 0; nt3 < 8; nt3++) {
                    uint2 b = *(const uint2*)(w3p + (kt * 8 + nt3) * 64);
                    mma16(acc3[nt3], af, b.x, b.y);
                }
            }
        }

        // ---- epilogue: +b3; solo fast STG, else sign-split atomics ----
        #pragma unroll
        for (int half = 0; half < 2; half++) {
            int r = half ? r1 : r0;
            size_t rb = (size_t)(r >> 1) * 64;
            if (r & 1) {
                float* dst = pooled + rb;
                #pragma unroll
                for (int nt3 = 0; nt3 < 8; nt3++) {
                    int col = nt3 * 8 + 2 * tig;
                    float2 val;
                    val.x = acc3[nt3][2 * half]     + smf[SB3 + col];
                    val.y = acc3[nt3][2 * half + 1] + smf[SB3 + col + 1];
                    *(float2*)(dst + col) = val;
                }
            } else {
                float* dst = pooled + rb;
                #pragma unroll
                for (int nt3 = 0; nt3 < 8; nt3++) {
                    int col = nt3 * 8 + 2 * tig;
                    atomic_fmax(dst + col,     acc3[nt3][2 * half]     + smf[SB3 + col]);
                    atomic_fmax(dst + col + 1, acc3[nt3][2 * half + 1] + smf[SB3 + col + 1]);
                }
            }
        }

        grp = ngrp;
        r0 = nr0; r1 = nr1;
    }
}

// ---------------- host launcher ----------------
extern "C" void kernel_launch(void* const* d_in, const int* in_sizes, int n_in,
                              void* d_out, int out_size) {
    const float* pt_fea = (const float*)d_in[0];
    const int*   xy     = (const int*)d_in[1];
    const float* W1     = (const float*)d_in[2];
    const float* b1     = (const float*)d_in[3];
    const float* W2     = (const float*)d_in[4];
    const float* b2     = (const float*)d_in[5];
    const float* W3     = (const float*)d_in[6];
    const float* b3     = (const float*)d_in[7];

    int M;
    float* unq_out;
    float* pooled;
    if (out_size % 67 == 0) {
        M = out_size / 67;
        unq_out = (float*)d_out;
        pooled = (float*)d_out + (size_t)3 * M;
    } else {
        M = out_size / 64;
        unq_out = nullptr;
        pooled = (float*)d_out;
    }

    cudaFuncSetAttribute(k_mlp, cudaFuncAttributeMaxDynamicSharedMemorySize, SMEM_BYTES);

    k_mark<<<(PTOT + 255) / 256, 256>>>(xy);
    k_scan1<<<NCELL / 1024, 1024>>>();
    k_scan3<<<NCELL / 1024, 1024>>>(unq_out, (uint2*)pooled);
    k_mlp<<<NSM, NTHR, SMEM_BYTES>>>(pt_fea, xy, W1, b1, W2, b2, W3, b3, pooled);
}

// round 13
// speedup vs baseline: 1.1092x; 1.0136x over previous
#include <cuda_runtime.h>
#include <cstdint>

#define GRIDW 480
#define NPTS 100000
#define PTOT 400000
#define NCELL (4*GRIDW*GRIDW)      // 921600
#define NSM 148
#define NTHR 512
#define NWARPS (NSM*16)            // 2368
#define NGROUP (PTOT/16)           // 25000 warp-tiles of 16 points

// ---------------- smem layout (u32 offsets) ----------------
#define SW2 0        // W2 B-frags fp16: 4nc x 8ks x 8nt x 64 = 16384 u32
#define SW3 16384    // W3 B-frags fp16: 4nc x 4kt x 8nt x 64 = 8192 u32
#define SW1 24576    // 3*128 f32
#define SB1 24960    // 128 f32
#define SB2H 25088   // packed fp16x2 bias pairs: (nc*8+nt)*4+tig -> 128 u32
#define SB3 25216    // 64 f32
#define SMEM_U32 25280
#define SMEM_BYTES (SMEM_U32*4)    // 101120 B

// ---------------- device scratch ----------------
__device__ int g_cnt[NCELL];      // zero at load; self-resetting (scan1 clears)
__device__ int g_rank[NCELL];     // scan1: partial|flags ; scan3: (rank<<1)|solo
__device__ int g_bsum[1024];

// ---------------- helpers ----------------
__device__ __forceinline__ uint32_t f2h2(float lo, float hi) {
    uint32_t r;
    asm("cvt.rn.f16x2.f32 %0, %1, %2;" : "=r"(r) : "f"(hi), "f"(lo));
    return r;
}
__device__ __forceinline__ unsigned short f2h(float f) {
    unsigned short h;
    asm("cvt.rn.f16.f32 %0, %1;" : "=h"(h) : "f"(f));
    return h;
}
__device__ __forceinline__ uint32_t hadd2(uint32_t a, uint32_t b) {
    uint32_t r;
    asm("add.rn.f16x2 %0, %1, %2;" : "=r"(r) : "r"(a), "r"(b));
    return r;
}
__device__ __forceinline__ uint32_t hrelu2(uint32_t a) {
    uint32_t r;
    asm("max.f16x2 %0, %1, %2;" : "=r"(r) : "r"(a), "r"(0u));
    return r;
}
__device__ __forceinline__ void mma16(float* d, const uint32_t* a, uint32_t b0, uint32_t b1) {
    asm volatile("mma.sync.aligned.m16n8k16.row.col.f32.f16.f16.f32 "
        "{%0,%1,%2,%3},{%4,%5,%6,%7},{%8,%9},{%0,%1,%2,%3};"
        : "+f"(d[0]), "+f"(d[1]), "+f"(d[2]), "+f"(d[3])
        : "r"(a[0]), "r"(a[1]), "r"(a[2]), "r"(a[3]), "r"(b0), "r"(b1));
}
__device__ __forceinline__ void atomic_fmax(float* addr, float v) {
    if (v >= 0.0f) atomicMax((int*)addr, __float_as_int(v));
    else atomicMin((unsigned int*)addr, __float_as_uint(v));
}

// ---------------- small kernels ----------------
__global__ void k_mark(const int* __restrict__ xy) {
    int p = blockIdx.x * blockDim.x + threadIdx.x;
    if (p < PTOT) {
        int2 v = ((const int2*)xy)[p];
        int b = p / NPTS;
        atomicAdd(&g_cnt[(b * GRIDW + v.x) * GRIDW + v.y], 1);
    }
}

// per-block exclusive scan of occupancy; packs occ/solo flags; zeroes g_cnt for next replay
__global__ void k_scan1() {
    __shared__ int ws[32];
    int i = blockIdx.x * 1024 + threadIdx.x;
    int lane = threadIdx.x & 31, wid = threadIdx.x >> 5;
    int c = g_cnt[i];
    if (c) g_cnt[i] = 0;                    // self-reset (write only if dirty)
    int v = (c != 0);
    unsigned int m = __ballot_sync(0xffffffffu, v);
    int excl = __popc(m & ((1u << lane) - 1u));
    if (lane == 31) ws[wid] = excl + v;
    __syncthreads();
    if (wid == 0) {
        int x = ws[lane];
        #pragma unroll
        for (int d = 1; d < 32; d <<= 1) {
            int o = __shfl_up_sync(0xffffffffu, x, d);
            if (lane >= d) x += o;
        }
        ws[lane] = x;
    }
    __syncthreads();
    int partial = excl + (wid ? ws[wid - 1] : 0);
    g_rank[i] = partial | (v << 16) | ((c == 1) << 17);
    if (threadIdx.x == 1023) g_bsum[blockIdx.x] = ws[31];
}

// finalize ranks (block offset computed inline from g_bsum), write unq rows,
// and -inf-init pooled rows of non-solo voxels (warp-cooperative, coalesced).
__global__ void k_scan3(float* unq_out, uint2* pooled) {
    __shared__ int ws[32];
    __shared__ int s_off;
    int t = threadIdx.x;
    int lane = t & 31, wid = t >> 5;

    int v = (t < blockIdx.x && t < 900) ? g_bsum[t] : 0;
    #pragma unroll
    for (int d = 16; d > 0; d >>= 1)
        v += __shfl_xor_sync(0xffffffffu, v, d);
    if (lane == 0) ws[wid] = v;
    __syncthreads();
    if (wid == 0) {
        int x = ws[lane];
        #pragma unroll
        for (int d = 16; d > 0; d >>= 1)
            x += __shfl_xor_sync(0xffffffffu, x, d);
        if (lane == 0) s_off = x;
    }
    __syncthreads();
    int off = s_off;

    int i = blockIdx.x * 1024 + t;
    int packed = g_rank[i];
    int occ = (packed >> 16) & 1;
    int solo = (packed >> 17) & 1;
    int r = (packed & 0xFFFF) + off;
    if (occ) {
        g_rank[i] = (r << 1) | solo;
        if (unq_out) {
            int b = i / (GRIDW * GRIDW);
            int rem = i - b * GRIDW * GRIDW;
            unq_out[3 * r + 0] = (float)b;
            unq_out[3 * r + 1] = (float)(rem / GRIDW);
            unq_out[3 * r + 2] = (float)(rem % GRIDW);
        }
    }
    unsigned int nm = __ballot_sync(0xffffffffu, occ && !solo);
    uint2 ninf = make_uint2(0xff800000u, 0xff800000u);
    while (nm) {
        int src = __ffs(nm) - 1;
        nm &= nm - 1;
        int rr = __shfl_sync(0xffffffffu, r, src);
        pooled[(size_t)rr * 32 + lane] = ninf;
    }
}

// ---------------- fused fp16 mma.sync MLP, M=16/warp, 16 warps, lean instr stream ----
__global__ void __launch_bounds__(NTHR, 1)
k_mlp(const float* __restrict__ pt_fea, const int* __restrict__ xy,
      const float* __restrict__ W1g, const float* __restrict__ b1g,
      const float* __restrict__ W2g, const float* __restrict__ b2g,
      const float* __restrict__ W3g, const float* __restrict__ b3g,
      float* __restrict__ pooled) {
    extern __shared__ uint32_t sm[];
    float* smf = (float*)sm;
    int t = threadIdx.x;

    // ---- stage W2 as fp16 B-frags: sm[SW2 + ((nc*8+ks)*8+nt)*64 + lane*2 + j] ----
    for (int idx = t; idx < 16384; idx += NTHR) {
        int j = idx & 1, lane = (idx >> 1) & 31, nt = (idx >> 6) & 7,
            ks = (idx >> 9) & 7, nc = idx >> 12;
        int k = ks * 16 + (lane & 3) * 2 + j * 8;
        int n = nc * 64 + nt * 8 + (lane >> 2);
        sm[SW2 + idx] = (uint32_t)f2h(W2g[k * 256 + n]) |
                        ((uint32_t)f2h(W2g[(k + 1) * 256 + n]) << 16);
    }
    // ---- stage W3 as fp16 B-frags: sm[SW3 + ((nc*4+kt)*8+nt)*64 + lane*2 + j] ----
    for (int idx = t; idx < 8192; idx += NTHR) {
        int j = idx & 1, lane = (idx >> 1) & 31, nt = (idx >> 6) & 7,
            kt = (idx >> 9) & 3, nc = idx >> 11;
        int k = nc * 64 + kt * 16 + (lane & 3) * 2 + j * 8;
        int n = nt * 8 + (lane >> 2);
        sm[SW3 + idx] = (uint32_t)f2h(W3g[k * 64 + n]) |
                        ((uint32_t)f2h(W3g[(k + 1) * 64 + n]) << 16);
    }
    for (int i = t; i < 384; i += NTHR) smf[SW1 + i] = W1g[i];
    if (t < 128) smf[SB1 + t] = b1g[t];
    // packed fp16x2 layer-2 bias pairs: idx = (nc*8+nt)*4 + tig -> (b2[col], b2[col+1])
    if (t < 128) {
        int tig = t & 3, nt = (t >> 2) & 7, nc = t >> 5;
        int col = nc * 64 + nt * 8 + 2 * tig;
        sm[SB2H + t] = (uint32_t)f2h(b2g[col]) | ((uint32_t)f2h(b2g[col + 1]) << 16);
    }
    if (t < 64) smf[SB3 + t] = b3g[t];
    __syncthreads();

    const int lane = t & 31;
    const int gq = lane >> 2, tig = lane & 3;
    const int warp = blockIdx.x * (NTHR / 32) + (t >> 5);
    const int2* __restrict__ xy2 = (const int2*)xy;

    // ---- prologue: resolve first tile's rank chain up front ----
    int grp = warp;
    int r0 = 0, r1 = 0;
    {
        int p0 = grp * 16 + gq, p1 = p0 + 8;
        int2 v0 = xy2[p0], v1 = xy2[p1];
        r0 = g_rank[((p0 / NPTS) * GRIDW + v0.x) * GRIDW + v0.y];
        r1 = g_rank[((p1 / NPTS) * GRIDW + v1.x) * GRIDW + v1.y];
    }

    #pragma unroll 1
    while (grp < NGROUP) {
        int p0 = grp * 16 + gq, p1 = p0 + 8;
        float x00 = pt_fea[p0 * 3], x01 = pt_fea[p0 * 3 + 1], x02 = pt_fea[p0 * 3 + 2];
        float x10 = pt_fea[p1 * 3], x11 = pt_fea[p1 * 3 + 1], x12 = pt_fea[p1 * 3 + 2];

        // prefetch next tile's xy (first link of the rank chain)
        int ngrp = grp + NWARPS;
        bool more = ngrp < NGROUP;
        int2 nv0, nv1;
        if (more) {
            int q0 = ngrp * 16 + gq;
            nv0 = xy2[q0]; nv1 = xy2[q0 + 8];
        }

        // ---- layer 1 -> fp16 A fragments (m16k16): A[ks][0..3] (float2 loads) ----
        uint32_t A[8][4];
        #pragma unroll
        for (int ks = 0; ks < 8; ks++) {
            int c0 = ks * 16 + tig * 2;
            #pragma unroll
            for (int h = 0; h < 2; h++) {
                int c = c0 + h * 8;   // always even
                float2 wa = *(const float2*)(smf + SW1 + c);
                float2 wb = *(const float2*)(smf + SW1 + 128 + c);
                float2 wc = *(const float2*)(smf + SW1 + 256 + c);
                float2 bb = *(const float2*)(smf + SB1 + c);
                float p0a = fmaxf(fmaf(x02, wc.x, fmaf(x01, wb.x, fmaf(x00, wa.x, bb.x))), 0.f);
                float p0b = fmaxf(fmaf(x02, wc.y, fmaf(x01, wb.y, fmaf(x00, wa.y, bb.y))), 0.f);
                float p1a = fmaxf(fmaf(x12, wc.x, fmaf(x11, wb.x, fmaf(x10, wa.x, bb.x))), 0.f);
                float p1b = fmaxf(fmaf(x12, wc.y, fmaf(x11, wb.y, fmaf(x10, wa.y, bb.y))), 0.f);
                A[ks][0 + h * 2] = f2h2(p0a, p0b);
                A[ks][1 + h * 2] = f2h2(p1a, p1b);
            }
        }

        // prefetch next tile's ranks (second link; xy arrived during layer 1)
        int nr0 = 0, nr1 = 0;
        if (more) {
            int q0 = ngrp * 16 + gq, q1 = q0 + 8;
            nr0 = g_rank[((q0 / NPTS) * GRIDW + nv0.x) * GRIDW + nv0.y];
            nr1 = g_rank[((q1 / NPTS) * GRIDW + nv1.x) * GRIDW + nv1.y];
        }

        float acc3[8][4];
        #pragma unroll
        for (int n = 0; n < 8; n++)
            #pragma unroll
            for (int q = 0; q < 4; q++) acc3[n][q] = 0.f;

        #pragma unroll 1
        for (int nc = 0; nc < 4; nc++) {
            const uint32_t* w2p = sm + SW2 + nc * 4096 + lane * 2;
            const uint32_t* w3p = sm + SW3 + nc * 2048 + lane * 2;
            const uint32_t* b2h = sm + SB2H + nc * 32 + tig;
            #pragma unroll
            for (int kt = 0; kt < 4; kt++) {
                int ntA = 2 * kt, ntB = 2 * kt + 1;
                float accA[4] = {0.f, 0.f, 0.f, 0.f};
                float accB[4] = {0.f, 0.f, 0.f, 0.f};
                #pragma unroll
                for (int ks = 0; ks < 8; ks++) {
                    uint2 bA = *(const uint2*)(w2p + (ks * 8 + ntA) * 64);
                    mma16(accA, A[ks], bA.x, bA.y);
                    uint2 bB = *(const uint2*)(w2p + (ks * 8 + ntB) * 64);
                    mma16(accB, A[ks], bB.x, bB.y);
                }
                // fp16-domain convert: pack, add packed bias, relu
                uint32_t bAh = b2h[ntA * 4];
                uint32_t bBh = b2h[ntB * 4];
                uint32_t af[4];
                af[0] = hrelu2(hadd2(f2h2(accA[0], accA[1]), bAh));
                af[1] = hrelu2(hadd2(f2h2(accA[2], accA[3]), bAh));
                af[2] = hrelu2(hadd2(f2h2(accB[0], accB[1]), bBh));
                af[3] = hrelu2(hadd2(f2h2(accB[2], accB[3]), bBh));
                #pragma unroll
                for (int nt3 = 0; nt3 < 8; nt3++) {
                    uint2 b = *(const uint2*)(w3p + (kt * 8 + nt3) * 64);
                    mma16(acc3[nt3], af, b.x, b.y);
                }
            }
        }

        // ---- epilogue: +b3; solo fast STG, else sign-split atomics ----
        #pragma unroll
        for (int half = 0; half < 2; half++) {
            int r = half ? r1 : r0;
            size_t rb = (size_t)(r >> 1) * 64;
            if (r & 1) {
                float* dst = pooled + rb;
                #pragma unroll
                for (int nt3 = 0; nt3 < 8; nt3++) {
                    int col = nt3 * 8 + 2 * tig;
                    float2 val;
                    val.x = acc3[nt3][2 * half]     + smf[SB3 + col];
                    val.y = acc3[nt3][2 * half + 1] + smf[SB3 + col + 1];
                    *(float2*)(dst + col) = val;
                }
            } else {
                float* dst = pooled + rb;
                #pragma unroll
                for (int nt3 = 0; nt3 < 8; nt3++) {
                    int col = nt3 * 8 + 2 * tig;
                    atomic_fmax(dst + col,     acc3[nt3][2 * half]     + smf[SB3 + col]);
                    atomic_fmax(dst + col + 1, acc3[nt3][2 * half + 1] + smf[SB3 + col + 1]);
                }
            }
        }

        grp = ngrp;
        r0 = nr0; r1 = nr1;
    }
}

// ---------------- host launcher ----------------
extern "C" void kernel_launch(void* const* d_in, const int* in_sizes, int n_in,
                              void* d_out, int out_size) {
    const float* pt_fea = (const float*)d_in[0];
    const int*   xy     = (const int*)d_in[1];
    const float* W1     = (const float*)d_in[2];
    const float* b1     = (const float*)d_in[3];
    const float* W2     = (const float*)d_in[4];
    const float* b2     = (const float*)d_in[5];
    const float* W3     = (const float*)d_in[6];
    const float* b3     = (const float*)d_in[7];

    int M;
    float* unq_out;
    float* pooled;
    if (out_size % 67 == 0) {
        M = out_size / 67;
        unq_out = (float*)d_out;
        pooled = (float*)d_out + (size_t)3 * M;
    } else {
        M = out_size / 64;
        unq_out = nullptr;
        pooled = (float*)d_out;
    }

    cudaFuncSetAttribute(k_mlp, cudaFuncAttributeMaxDynamicSharedMemorySize, SMEM_BYTES);

    k_mark<<<(PTOT + 255) / 256, 256>>>(xy);
    k_scan1<<<NCELL / 1024, 1024>>>();
    k_scan3<<<NCELL / 1024, 1024>>>(unq_out, (uint2*)pooled);
    k_mlp<<<NSM, NTHR, SMEM_BYTES>>>(pt_fea, xy, W1, b1, W2, b2, W3, b3, pooled);
}